// round 13
// baseline (speedup 1.0000x reference)
#include <cuda_runtime.h>
#include <cstdint>

#define NUM_EDGE_TYPES 38
#define NUM_NODE_TYPES 4
#define HIDDEN 64
#define N_NODES 100000
#define N_EDGES 1600000
#define NUM_COMBOS (NUM_EDGE_TYPES * NUM_NODE_TYPES * NUM_NODE_TYPES)  // 608
#define NTP_WORDS (N_NODES / 16)  // 2-bit packed node types
#define SRC_MASK 0x1FFFF          // src < 100000 < 2^17; combo in bits [17,27)

#define BIN_SHIFT 14
#define BIN 16384                 // src-bin width (64 KB fp32 staged)
#define NBINS 7                   // ceil(100000 / 16384)
#define CAP 20                    // per-(bin,node) slot cap; Poisson(2.6) tail @20 ~ 1e-12

// Scratch (device globals — no allocation allowed).
__device__ float    g_lut[NUM_COMBOS];
__device__ unsigned g_ntp[NTP_WORDS];
__device__ int      g_cnt[NBINS * N_NODES];          // cursors per (bin, dst)
__device__ unsigned g_slot[NBINS * CAP * N_NODES];   // [(q*CAP+i)*N + v] = src | combo<<17
__device__ float    g_S[N_NODES];                    // aggr after hop 1
__device__ float    g_A2[N_NODES];                   // aggr after hop 2
__device__ float    g_A3[N_NODES];                   // aggr after hop 3

// Monotonic (replay-safe) grid barrier. Never reset.
__device__ unsigned g_arrive = 0;
__device__ volatile unsigned g_release = 0;

__device__ __forceinline__ void grid_barrier(unsigned nb) {
    __syncthreads();
    if (threadIdx.x == 0) {
        __threadfence();
        unsigned ticket = atomicAdd(&g_arrive, 1u);
        unsigned target = ticket - (ticket % nb) + nb;
        if (ticket % nb == nb - 1u) {
            g_release = target;
        } else {
            while (*(volatile unsigned*)&g_release < target) { }
        }
        __threadfence();
    }
    __syncthreads();
}

__device__ __forceinline__ int ntp_lookup(int id) {
    return (int)((__ldg(&g_ntp[id >> 4]) >> ((id & 15) << 1)) & 3u);
}

__device__ __forceinline__ void cp_async16(void* sdst, const void* gsrc) {
    uint32_t sa = (uint32_t)__cvta_generic_to_shared(sdst);
    asm volatile("cp.async.cg.shared.global [%0], [%1], 16;" :: "r"(sa), "l"(gsrc));
}
__device__ __forceinline__ void cp_commit() { asm volatile("cp.async.commit_group;"); }
__device__ __forceinline__ void cp_wait_all() { asm volatile("cp.async.wait_group 0;" ::: "memory"); }

// ---------------------------------------------------------------------------
// K1: LUT + pack node types + zero cursors.
// ---------------------------------------------------------------------------
__global__ void k_init(const float* __restrict__ W1, const float* __restrict__ b1,
                       const float* __restrict__ W2, const float* __restrict__ b2,
                       const int* __restrict__ ntyp) {
    int gt = blockIdx.x * blockDim.x + threadIdx.x;
    int NT = gridDim.x * blockDim.x;

    if (gt < NUM_COMBOS * 32) {          // 32 lanes per combo, shuffle reduce
        int combo = gt >> 5, lane = gt & 31;
        int et = combo >> 4, ht = (combo >> 2) & 3, tt = combo & 3;
        float acc = 0.f;
#pragma unroll
        for (int j = 0; j < 2; j++) {
            int k = lane + j * 32;
            float h = W1[et * HIDDEN + k]
                    + W1[(NUM_EDGE_TYPES + ht) * HIDDEN + k]
                    + W1[(NUM_EDGE_TYPES + NUM_NODE_TYPES + tt) * HIDDEN + k]
                    + b1[k];
            float h3 = h * h * h;        // jax.nn.gelu default (tanh approximation)
            float g = 0.5f * h * (1.f + tanhf(0.7978845608028654f * (h + 0.044715f * h3)));
            acc = fmaf(g, W2[k], acc);
        }
#pragma unroll
        for (int o = 16; o > 0; o >>= 1) acc += __shfl_xor_sync(0xffffffffu, acc, o);
        if (lane == 0) g_lut[combo] = 1.f / (1.f + expf(-(acc + b2[0])));
    }

    for (int w = gt; w < NTP_WORDS; w += NT) {
        const int* nt4 = ntyp + (w << 4);
        unsigned p = 0;
#pragma unroll
        for (int j = 0; j < 4; j++) {
            int4 q = *reinterpret_cast<const int4*>(nt4 + j * 4);
            p |= (unsigned)(q.x & 3) << ((j * 4 + 0) << 1);
            p |= (unsigned)(q.y & 3) << ((j * 4 + 1) << 1);
            p |= (unsigned)(q.z & 3) << ((j * 4 + 2) << 1);
            p |= (unsigned)(q.w & 3) << ((j * 4 + 3) << 1);
        }
        g_ntp[w] = p;
    }

    for (int v = gt; v < NBINS * N_NODES; v += NT) g_cnt[v] = 0;
}

// ---------------------------------------------------------------------------
// K2: build src-binned in-CSR. 2 random ops/edge (cursor ATOMG + slot store).
// ---------------------------------------------------------------------------
__global__ void k_build(const int* __restrict__ src, const int* __restrict__ dst,
                        const int* __restrict__ etyp) {
    int i = (blockIdx.x * blockDim.x + threadIdx.x) * 4;
    if (i >= N_EDGES) return;

    int4 s = *reinterpret_cast<const int4*>(src + i);
    int4 d = *reinterpret_cast<const int4*>(dst + i);
    int4 t = *reinterpret_cast<const int4*>(etyp + i);

    unsigned c0 = (unsigned)((t.x << 4) + (ntp_lookup(s.x) << 2) + ntp_lookup(d.x));
    unsigned c1 = (unsigned)((t.y << 4) + (ntp_lookup(s.y) << 2) + ntp_lookup(d.y));
    unsigned c2 = (unsigned)((t.z << 4) + (ntp_lookup(s.z) << 2) + ntp_lookup(d.z));
    unsigned c3 = (unsigned)((t.w << 4) + (ntp_lookup(s.w) << 2) + ntp_lookup(d.w));

    int q0 = s.x >> BIN_SHIFT, q1 = s.y >> BIN_SHIFT;
    int q2 = s.z >> BIN_SHIFT, q3 = s.w >> BIN_SHIFT;

    int p0 = atomicAdd(&g_cnt[q0 * N_NODES + d.x], 1);
    int p1 = atomicAdd(&g_cnt[q1 * N_NODES + d.y], 1);
    int p2 = atomicAdd(&g_cnt[q2 * N_NODES + d.z], 1);
    int p3 = atomicAdd(&g_cnt[q3 * N_NODES + d.w], 1);

    if (p0 < CAP) g_slot[(q0 * CAP + p0) * N_NODES + d.x] = (unsigned)s.x | (c0 << 17);
    if (p1 < CAP) g_slot[(q1 * CAP + p1) * N_NODES + d.y] = (unsigned)s.y | (c1 << 17);
    if (p2 < CAP) g_slot[(q2 * CAP + p2) * N_NODES + d.z] = (unsigned)s.z | (c2 << 17);
    if (p3 < CAP) g_slot[(q3 * CAP + p3) * N_NODES + d.w] = (unsigned)s.w | (c3 << 17);
}

// ---------------------------------------------------------------------------
// K3 (persistent, 1 CTA/SM): S-pass + 3 hops. Random gathers hit SMEM.
//   Each CTA owns npc consecutive nodes; each hop stages all 7 src-bins of
//   in[] through double-buffered cp.async while gathering the previous bin.
// ---------------------------------------------------------------------------
__global__ void __launch_bounds__(1024, 1) k_main(float* __restrict__ out,
                                                  unsigned NB) {
    extern __shared__ float sh[];              // 2 * BIN floats (128 KB)
    __shared__ float lut_s[NUM_COMBOS];
    for (int k = threadIdx.x; k < NUM_COMBOS; k += 1024) lut_s[k] = g_lut[k];

    int npc = (N_NODES + gridDim.x - 1) / gridDim.x;
    int v = blockIdx.x * npc + threadIdx.x;
    bool act = ((int)threadIdx.x < npc) && (v < N_NODES);

    // Per-bin slot counts, cached in registers for all 4 phases.
    int cq[NBINS];
#pragma unroll
    for (int q = 0; q < NBINS; q++)
        cq[q] = act ? min(g_cnt[q * N_NODES + v], CAP) : 0;

    __syncthreads();

    // ---- S-pass: S[v] = sum of lut[combo] over in-edges ----
    float sv = 0.f;
    if (act) {
#pragma unroll
        for (int q = 0; q < NBINS; q++) {
            int cc = cq[q];
            float a0 = 0.f, a1 = 0.f;
            int i = 0;
            for (; i + 1 < cc; i += 2) {
                unsigned w0 = g_slot[(q * CAP + i    ) * N_NODES + v];
                unsigned w1 = g_slot[(q * CAP + i + 1) * N_NODES + v];
                a0 += lut_s[w0 >> 17];
                a1 += lut_s[w1 >> 17];
            }
            if (i < cc) a0 += lut_s[g_slot[(q * CAP + i) * N_NODES + v] >> 17];
            sv += a0 + a1;
        }
        g_S[v] = sv;
    }
    grid_barrier(NB);

    // ---- 3 hops: out_h[v] = S[v] + sum in_h[src] (src gathered from smem) ----
    const float* in = g_S;
#pragma unroll
    for (int h = 0; h < 3; h++) {
        float* op = (h == 0) ? g_A2 : (h == 1) ? g_A3 : out;
        float acc = 0.f;

        // Prologue: stage bin 0.
        {
            int valid4 = min(BIN, N_NODES) / 4;    // bin 0 always full here
            const float4* gp = reinterpret_cast<const float4*>(in);
            float4* sp = reinterpret_cast<float4*>(sh);
            for (int k = threadIdx.x; k < valid4; k += 1024)
                cp_async16(sp + k, gp + k);
            cp_commit();
        }

#pragma unroll
        for (int q = 0; q < NBINS; q++) {
            cp_wait_all();
            __syncthreads();                        // staged bin q visible to all

            if (q + 1 < NBINS) {                    // stage next bin into other buffer
                int lo = (q + 1) << BIN_SHIFT;
                int valid4 = (min(BIN, N_NODES - lo) + 3) / 4;
                const float4* gp = reinterpret_cast<const float4*>(in + lo);
                float4* sp = reinterpret_cast<float4*>(sh + ((q + 1) & 1) * BIN);
                for (int k = threadIdx.x; k < valid4; k += 1024)
                    cp_async16(sp + k, gp + k);
                cp_commit();
            }

            if (act) {
                const float* buf = sh + (q & 1) * BIN;
                int lo = q << BIN_SHIFT;
                int cc = cq[q];
                float a0 = 0.f, a1 = 0.f;
                int i = 0;
                for (; i + 1 < cc; i += 2) {
                    unsigned w0 = g_slot[(q * CAP + i    ) * N_NODES + v];
                    unsigned w1 = g_slot[(q * CAP + i + 1) * N_NODES + v];
                    a0 += buf[(int)(w0 & SRC_MASK) - lo];
                    a1 += buf[(int)(w1 & SRC_MASK) - lo];
                }
                if (i < cc)
                    a0 += buf[(int)(g_slot[(q * CAP + i) * N_NODES + v] & SRC_MASK) - lo];
                acc += a0 + a1;
            }
            __syncthreads();                        // gathers done before buffer reuse
        }

        if (act) op[v] = sv + acc;
        grid_barrier(NB);                           // op complete before next staging
        in = op;
    }
}

extern "C" void kernel_launch(void* const* d_in, const int* in_sizes, int n_in,
                              void* d_out, int out_size) {
    const int* edge_index = (const int*)d_in[0];   // [2, E]
    const int* edge_type  = (const int*)d_in[1];   // [E]
    const int* node_type  = (const int*)d_in[2];   // [N]
    const float* W1 = (const float*)d_in[3];
    const float* b1 = (const float*)d_in[4];
    const float* W2 = (const float*)d_in[5];
    const float* b2 = (const float*)d_in[6];
    float* out = (float*)d_out;                    // [N, 1]

    const int* src = edge_index;
    const int* dst = edge_index + N_EDGES;

    int dev = 0, sm = 148;
    cudaGetDevice(&dev);
    cudaDeviceGetAttribute(&sm, cudaDevAttrMultiProcessorCount, dev);

    const int TB = 256;
    const int initBlocks = 592;
    const int buildBlocks = (N_EDGES / 4 + TB - 1) / TB;  // 1563
    const size_t shBytes = 2 * BIN * sizeof(float);       // 128 KB -> 1 CTA/SM

    cudaFuncSetAttribute(k_main, cudaFuncAttributeMaxDynamicSharedMemorySize,
                         (int)shBytes);

    unsigned NB = (unsigned)sm;    // 1 CTA/SM (forced by 128 KB smem) -> resident

    k_init<<<initBlocks, TB>>>(W1, b1, W2, b2, node_type);
    k_build<<<buildBlocks, TB>>>(src, dst, edge_type);
    k_main<<<NB, 1024, shBytes>>>(out, NB);
}